// round 17
// baseline (speedup 1.0000x reference)
#include <cuda_runtime.h>
#include <math.h>

#define RCR 5.2f
#define RCA 3.5f
#define NSP 4
#define NATOMS 32
#define NSHFR 16
#define NSHFA 4
#define NSHFZ 8
#define NPAIRBIN 10
#define RAD_FEAT (NSP*NSHFR)            /* 64  */
#define ANG_FEAT (NPAIRBIN*NSHFA*NSHFZ) /* 320 */
#define OUT_FEAT (RAD_FEAT+ANG_FEAT)    /* 384 */
#define KMAX 240                         /* packed pair-groups: 480 slots >= 465+10 pads */
#define LOG2E 1.4426950408889634f
#define SQRT095 0.97467943448089633f

typedef unsigned long long ull;

__device__ __forceinline__ float ex2f(float x){ float y; asm("ex2.approx.ftz.f32 %0, %1;":"=f"(y):"f"(x)); return y; }
__device__ __forceinline__ float lg2f(float x){ float y; asm("lg2.approx.ftz.f32 %0, %1;":"=f"(y):"f"(x)); return y; }
__device__ __forceinline__ float sqrt_apx(float x){ float y; asm("sqrt.approx.ftz.f32 %0, %1;":"=f"(y):"f"(x)); return y; }
__device__ __forceinline__ float rsqrt_apx(float x){ float y; asm("rsqrt.approx.ftz.f32 %0, %1;":"=f"(y):"f"(x)); return y; }

__device__ __forceinline__ ull pk2(float lo, float hi){ ull r; asm("mov.b64 %0,{%1,%2};":"=l"(r):"f"(lo),"f"(hi)); return r; }
__device__ __forceinline__ void upk2(ull v, float& lo, float& hi){ asm("mov.b64 {%0,%1},%2;":"=f"(lo),"=f"(hi):"l"(v)); }
__device__ __forceinline__ ull fma2(ull a, ull b, ull c){ ull d; asm("fma.rn.f32x2 %0,%1,%2,%3;":"=l"(d):"l"(a),"l"(b),"l"(c)); return d; }
__device__ __forceinline__ ull mul2(ull a, ull b){ ull d; asm("mul.rn.f32x2 %0,%1,%2;":"=l"(d):"l"(a),"l"(b)); return d; }

// geometry: flat triangular enumeration over 128 threads; bin-sorted records
__device__ __forceinline__ void geometry_phase(
    int tid, int ncA, float nEtaA, float zoff,
    const float4* __restrict__ n4, const float* __restrict__ nlg,
    const int* __restrict__ nsp, const float* __restrict__ shfA,
    int* __restrict__ pos, float* __restrict__ csf, float* __restrict__ exf)
{
    const int P = (ncA * (ncA - 1)) >> 1;
    const float fn1 = (float)(2*ncA - 1);
    for (int g = tid; g < P; g += 128) {
        float sdisc = sqrtf(fmaf(fn1, fn1, (float)(-8*g)));
        int a = (int)(0.5f * (fn1 - sdisc));
        a = max(a, 0);
        while (a*(ncA-1) - ((a*(a-1))>>1) > g) a--;
        while ((a+1)*(ncA-1) - (((a+1)*a)>>1) <= g) a++;
        int q = g - (a*(ncA-1) - ((a*(a-1))>>1)) + a + 1;

        float4 A4 = n4[a];
        float4 B4 = n4[q];
        float c  = A4.x*B4.x + A4.y*B4.y + A4.z*B4.z;   // 0.95*cos(theta)
        float st = sqrt_apx(fmaf(-c, c, 1.0f));
        float dm = A4.w + B4.w;
        float lg = nlg[a] + nlg[q] + zoff;
        int sa = nsp[a], sq = nsp[q];
        int lo = min(sa, sq), hi = max(sa, sq);
        int pbin = lo*NSP - ((lo*(lo-1))>>1) + (hi - lo);
        int slot = atomicAdd(&pos[pbin], 1);
        int k = slot >> 1, h = slot & 1;
        csf[k*4 + h]     = c;
        csf[k*4 + 2 + h] = st;
        #pragma unroll
        for (int p = 0; p < NSHFA; p++) {
            float e = dm - shfA[p];
            exf[k*8 + p*2 + h] = ex2f(fmaf(nEtaA * e, e, lg));
        }
    }
}

// consumer: MUFU-free packed f32x2, warp w sweeps its quarter
__device__ __forceinline__ void consume_phase(
    int w, int lane, const int* __restrict__ soff,
    bool z32, float zeta, const ull* __restrict__ cs2,
    const ull* __restrict__ ex2a, float cZ, float sZ, int p_l,
    float* __restrict__ accA)
{
    int off[NPAIRBIN+1];
    #pragma unroll
    for (int bb = 0; bb <= NPAIRBIN; bb++) off[bb] = soff[bb];
    const int Ptot = off[NPAIRBIN];

    const int g0 = ((Ptot * w) >> 2) & ~1;
    const int g1 = (w == 3) ? Ptot : (((Ptot * (w+1)) >> 2) & ~1);

    if (z32) {
        const ull cZ2 = pk2(cZ, cZ), sZ2 = pk2(sZ, sZ);
        const ull one2 = pk2(1.0f, 1.0f);
        #pragma unroll
        for (int bin = 0; bin < NPAIRBIN; bin++) {
            int lo = max(off[bin], g0), hi = min(off[bin+1], g1);
            if (lo >= hi) continue;
            int k0 = lo >> 1, k1 = hi >> 1;
            ull r2 = 0;
            #pragma unroll 2
            for (int k = k0; k < k1; k++) {
                ulonglong2 cs = *((const ulonglong2*)cs2 + k);  // LDS.128
                ull e2 = ex2a[k*4 + p_l];                       // LDS.64
                ull t2 = fma2(cs.y, sZ2, one2);
                ull y  = fma2(cs.x, cZ2, t2);
                ull yy2 = mul2(y, y);
                ull y4 = mul2(yy2, yy2);
                ull y8 = mul2(y4, y4);
                ull y16 = mul2(y8, y8);
                ull y32 = mul2(y16, y16);
                r2 = fma2(y32, e2, r2);
            }
            float rlo, rhi; upk2(r2, rlo, rhi);
            atomicAdd(&accA[bin*32 + lane], rlo + rhi);
        }
    } else {
        const float* csf = (const float*)cs2;
        const float* exf = (const float*)ex2a;
        #pragma unroll
        for (int bin = 0; bin < NPAIRBIN; bin++) {
            int lo = max(off[bin], g0), hi = min(off[bin+1], g1);
            if (lo >= hi) continue;
            float r = 0.0f;
            for (int g = lo; g < hi; g++) {
                int k = g >> 1, h = g & 1;
                float c  = csf[k*4 + h];
                float st = csf[k*4 + 2 + h];
                float e  = exf[k*8 + p_l*2 + h];
                float t = fmaf(st, sZ, 1.0f);
                float y = fmaf(c, cZ, t);
                float f1 = __powf(0.5f * y, zeta);
                r = fmaf(f1, e, r);
            }
            atomicAdd(&accA[bin*32 + lane], r);
        }
    }
}

__global__ __launch_bounds__(128) void aev_kernel(
    const float* __restrict__ coords,
    const float* __restrict__ etaR_p,
    const float* __restrict__ shfR_p,
    const float* __restrict__ etaA_p,
    const float* __restrict__ zeta_p,
    const float* __restrict__ shfA_p,
    const float* __restrict__ shfZ_p,
    const int*   __restrict__ species,
    float* __restrict__ out)
{
    __shared__ float s_cx[NATOMS], s_cy[NATOMS], s_cz[NATOMS];
    __shared__ int   s_sp[NATOMS];
    __shared__ float s_shfR[NSHFR], s_shfA[NSHFA];
    __shared__ float s_cosZ[NSHFZ], s_sinZ[NSHFZ];
    __shared__ __align__(16) float4 s_n4[2][NATOMS];
    __shared__ float  s_nlg[2][NATOMS];
    __shared__ int    s_nsp[2][NATOMS];
    __shared__ int    s_offs[2][NPAIRBIN+1];
    __shared__ int    s_cnt[2][NPAIRBIN];
    __shared__ int    s_ncA[2];
    __shared__ int    s_pos[NPAIRBIN];
    __shared__ __align__(16) ull s_cs[2*KMAX];       // shared arena (reused per atom)
    __shared__ __align__(16) ull s_ex[4*KMAX];
    __shared__ __align__(16) float s_accA[2][ANG_FEAT];
    __shared__ __align__(16) float s_accR[2][2][RAD_FEAT];  // [atom][warp-par][feat]
    __shared__ float  s_etaR, s_etaA, s_zeta;

    const int tid  = threadIdx.x;
    const int w    = tid >> 5;
    const int lane = tid & 31;
    const int slot = w >> 1;                 // atom handled by this warp in phase 1
    const int par  = w & 1;
    const int b    = blockIdx.x >> 4;        // 16 blocks per molecule
    const int ia0  = (blockIdx.x & 15) << 1; // first of 2 atoms for this block
    const int i    = ia0 + slot;             // this warp's atom (local idx)

    // ---- prologue ----
    if (tid < NATOMS) {
        s_cx[tid] = coords[(b*NATOMS + tid)*3 + 0];
        s_cy[tid] = coords[(b*NATOMS + tid)*3 + 1];
        s_cz[tid] = coords[(b*NATOMS + tid)*3 + 2];
        s_sp[tid] = species[b*NATOMS + tid];
    } else if (tid < 32 + NSHFR) {
        s_shfR[tid-32] = shfR_p[tid-32];
    } else if (tid < 48 + NSHFA) {
        s_shfA[tid-48] = shfA_p[tid-48];
    } else if (tid < 55) {
        if (tid == 52) s_etaR = etaR_p[0];
        if (tid == 53) s_etaA = etaA_p[0];
        if (tid == 54) s_zeta = zeta_p[0];
    } else if (tid >= 56 && tid < 64) {
        float z = shfZ_p[tid-56];
        s_cosZ[tid-56] = __cosf(z);
        s_sinZ[tid-56] = __sinf(z);
    }
    // zero angular banks (160 float4) and radial banks (64 float4)
    {
        float4 zz = make_float4(0.f,0.f,0.f,0.f);
        float4* za = (float4*)&s_accA[0][0];
        za[tid] = zz;
        if (tid < 32) za[128 + tid] = zz;
        float4* zr = (float4*)&s_accR[0][0][0];
        if (tid >= 32 && tid < 96) zr[tid-32] = zz;
    }
    __syncthreads();

    const float zeta  = s_zeta;
    const float nEtaR = -s_etaR * LOG2E;
    const float nEtaA = -s_etaA * LOG2E;
    const bool  z32   = (fabsf(zeta - 32.0f) < 1e-4f);
    const float zoff  = z32 ? -31.0f : 1.0f;
    const float PI_RCR = 3.14159265358979323846f / RCR;
    const float PI_RCA = 3.14159265358979323846f / RCA;

    // ---- phase 1: each warp handles ITS atom (distances, radial, ballots, bins) ----
    {
        const float cix = s_cx[i], ciy = s_cy[i], ciz = s_cz[i];
        const bool  valid_i = (s_sp[i] >= 0);

        float vx = s_cx[lane] - cix;
        float vy = s_cy[lane] - ciy;
        float vz = s_cz[lane] - ciz;
        float d2 = vx*vx + vy*vy + vz*vz;
        float inv = rsqrt_apx(fmaxf(d2, 1e-24f));
        float d   = d2 * inv;
        int   spl = s_sp[lane];
        int   spc = min(max(spl, 0), NSP-1);
        bool  pair_ok = valid_i && (spl >= 0) && (lane != i);

        // radial: 8 shifts per warp (pair of warps covers 16), staggered atomics
        if (pair_ok && d <= RCR) {
            float fcR  = fmaf(0.5f, __cosf(d * PI_RCR), 0.5f);
            float base = 0.25f * fcR;
            float* rad = &s_accR[slot][par][spc * NSHFR];
            int r0 = lane & 15;
            #pragma unroll
            for (int k = par*8; k < par*8 + 8; k++) {
                int r = (r0 + k) & 15;
                float e = d - s_shfR[r];
                atomicAdd(&rad[r], base * ex2f(nEtaR * (e * e)));
            }
        }

        bool isnb = pair_ok && (d <= RCA);
        unsigned ms[NSP];
        #pragma unroll
        for (int s = 0; s < NSP; s++)
            ms[s] = __ballot_sync(0xffffffffu, isnb && (spc == s));

        int o1 = __popc(ms[0]);
        int o2 = o1 + __popc(ms[1]);
        int o3 = o2 + __popc(ms[2]);
        int ncA = o3 + __popc(ms[3]);

        if (par == 0) {
            if (isnb) {
                unsigned lt = (1u << lane) - 1u;
                int base = (spc == 0) ? 0 : (spc == 1) ? o1 : (spc == 2) ? o2 : o3;
                int pos = base + __popc(ms[spc] & lt);
                float fcA = fmaf(0.5f, __cosf(d * PI_RCA), 0.5f);
                float us  = inv * SQRT095;
                s_n4[slot][pos]  = make_float4(vx*us, vy*us, vz*us, 0.5f*d);
                s_nlg[slot][pos] = lg2f(fcA);
                s_nsp[slot][pos] = spc;
            }
            // closed-form bin counts & even-padded offsets (registers)
            const int n0 = o1, n1 = o2-o1, n2 = o3-o2, n3 = ncA-o3;
            int cnt[NPAIRBIN];
            cnt[0] = (n0*(n0-1))>>1; cnt[1] = n0*n1; cnt[2] = n0*n2; cnt[3] = n0*n3;
            cnt[4] = (n1*(n1-1))>>1; cnt[5] = n1*n2; cnt[6] = n1*n3;
            cnt[7] = (n2*(n2-1))>>1; cnt[8] = n2*n3;
            cnt[9] = (n3*(n3-1))>>1;
            int off[NPAIRBIN+1];
            off[0] = 0;
            #pragma unroll
            for (int bb = 0; bb < NPAIRBIN; bb++) off[bb+1] = off[bb] + ((cnt[bb]+1) & ~1);

            if (lane == 0) s_ncA[slot] = ncA;
            if (lane <= NPAIRBIN) {
                int offv = 0, cv = 0;
                #pragma unroll
                for (int bb = 0; bb <= NPAIRBIN; bb++)
                    if (lane == bb) { offv = off[bb]; cv = (bb < NPAIRBIN) ? cnt[bb] : 0; }
                s_offs[slot][lane] = offv;
                if (lane < NPAIRBIN) {
                    s_cnt[slot][lane] = cv;
                    if (slot == 0) {
                        s_pos[lane] = offv;             // arena cursors for atom 0
                        if (cv & 1) {                    // pad record (atom 0)
                            int s = offv + cv, k = s >> 1, h = s & 1;
                            float* csf = (float*)s_cs;
                            float* exf = (float*)s_ex;
                            csf[k*4 + h] = 0.0f; csf[k*4 + 2 + h] = 0.0f;
                            #pragma unroll
                            for (int p = 0; p < NSHFA; p++) exf[k*8 + p*2 + h] = 0.0f;
                        }
                    }
                }
            }
        }
    }
    __syncthreads();

    // ---- radial epilogue (both atoms complete) ----
    {
        int aa = tid >> 6, f = tid & 63;
        out[(size_t)(b*NATOMS + ia0 + aa) * OUT_FEAT + f] =
            s_accR[aa][0][f] + s_accR[aa][1][f];
    }

    const int p_l = lane >> 3;
    const float cZ = s_cosZ[lane & 7];
    const float sZ = s_sinZ[lane & 7];

    // ---- atom 0: geometry ----
    geometry_phase(tid, s_ncA[0], nEtaA, zoff,
                   s_n4[0], s_nlg[0], s_nsp[0], s_shfA,
                   s_pos, (float*)s_cs, (float*)s_ex);
    __syncthreads();

    // ---- atom 0: consume; meanwhile init cursors for atom 1 ----
    if (tid < NPAIRBIN) s_pos[tid] = s_offs[1][tid];
    consume_phase(w, lane, s_offs[0], z32, zeta, s_cs, s_ex, cZ, sZ, p_l, s_accA[0]);
    __syncthreads();

    // ---- atom 1: pads then geometry (pad slots disjoint from fill slots) ----
    if (tid < NPAIRBIN) {
        int cv = s_cnt[1][tid];
        if (cv & 1) {
            int s = s_offs[1][tid] + cv, k = s >> 1, h = s & 1;
            float* csf = (float*)s_cs;
            float* exf = (float*)s_ex;
            csf[k*4 + h] = 0.0f; csf[k*4 + 2 + h] = 0.0f;
            #pragma unroll
            for (int p = 0; p < NSHFA; p++) exf[k*8 + p*2 + h] = 0.0f;
        }
    }
    geometry_phase(tid, s_ncA[1], nEtaA, zoff,
                   s_n4[1], s_nlg[1], s_nsp[1], s_shfA,
                   s_pos, (float*)s_cs, (float*)s_ex);
    __syncthreads();

    // ---- atom 1: consume ----
    consume_phase(w, lane, s_offs[1], z32, zeta, s_cs, s_ex, cZ, sZ, p_l, s_accA[1]);
    __syncthreads();

    // ---- angular epilogue: 640 floats over 128 threads ----
    #pragma unroll
    for (int f = tid; f < 2*ANG_FEAT; f += 128) {
        int aa = (f >= ANG_FEAT);
        int ff = f - aa*ANG_FEAT;
        out[(size_t)(b*NATOMS + ia0 + aa) * OUT_FEAT + RAD_FEAT + ff] = s_accA[aa][ff];
    }
}

extern "C" void kernel_launch(void* const* d_in, const int* in_sizes, int n_in,
                              void* d_out, int out_size)
{
    const float* coords = (const float*)d_in[0];
    const float* etaR   = (const float*)d_in[1];
    const float* shfR   = (const float*)d_in[2];
    const float* etaA   = (const float*)d_in[3];
    const float* zeta   = (const float*)d_in[4];
    const float* shfA   = (const float*)d_in[5];
    const float* shfZ   = (const float*)d_in[6];
    const int*   spec   = (const int*)d_in[7];
    float* out = (float*)d_out;

    int B = in_sizes[0] / (NATOMS*3);
    dim3 grid(B * 16);   // 2 atoms per block
    aev_kernel<<<grid, 128>>>(coords, etaR, shfR, etaA, zeta, shfA, shfZ, spec, out);
}